// round 1
// baseline (speedup 1.0000x reference)
#include <cuda_runtime.h>
#include <math.h>
#include <stdint.h>

#define NLEV 16
#define TBITS 19
#define TMASK ((1u << TBITS) - 1u)
#define NS 128
#define NRAYS 4096

#define P1 2654435761u
#define P2 805459861u

struct Cells { float c[NLEV]; };

__global__ __launch_bounds__(128)
void ngp_kernel(const float* __restrict__ rays,
                const float* __restrict__ t_rand,
                const float* __restrict__ tables,
                float* __restrict__ out,
                Cells cells)
{
    const int n = blockIdx.x;
    const int s = threadIdx.x;

    const float* ray = rays + n * 6;
    const float dirx = ray[0], diry = ray[1], dirz = ray[2];
    const float ox   = ray[3], oy   = ray[4], oz   = ray[5];

    const float step = 4.0f / 127.0f;   // (FAR-NEAR)/(NUM_SAMPLE-1)
    const float t    = 2.0f + s * step;

    const float px = ox + dirx * t;
    const float py = oy + diry * t;
    const float pz = oz + dirz * t;

    float feats[2 * NLEV];

    #pragma unroll
    for (int i = 0; i < NLEV; ++i) {
        const float cell = cells.c[i];

        const float qx = (px + 8.0f) / cell;
        const float qy = (py + 8.0f) / cell;
        const float qz = (pz + 8.0f) / cell;
        const float fx = floorf(qx), fy = floorf(qy), fz = floorf(qz);
        const int mix = (int)fx, miy = (int)fy, miz = (int)fz;

        // min_v = mi*cell + BB_MIN ; d = (p - min_v)/cell
        const float dx = (px - (fx * cell - 8.0f)) / cell;
        const float dy = (py - (fy * cell - 8.0f)) / cell;
        const float dz = (pz - (fz * cell - 8.0f)) / cell;

        const unsigned ux0 = (unsigned)mix;
        const unsigned ux1 = ux0 + 1u;
        const unsigned hy0 = (unsigned)miy * P1;
        const unsigned hy1 = hy0 + P1;
        const unsigned hz0 = (unsigned)miz * P2;
        const unsigned hz1 = hz0 + P2;

        // corner order follows VERTS rows: (vx,vy,vz) =
        // 000,001,010,011,100,101,110,111
        unsigned idx[8];
        idx[0] = (ux0 ^ hy0 ^ hz0) & TMASK;
        idx[1] = (ux0 ^ hy0 ^ hz1) & TMASK;
        idx[2] = (ux0 ^ hy1 ^ hz0) & TMASK;
        idx[3] = (ux0 ^ hy1 ^ hz1) & TMASK;
        idx[4] = (ux1 ^ hy0 ^ hz0) & TMASK;
        idx[5] = (ux1 ^ hy0 ^ hz1) & TMASK;
        idx[6] = (ux1 ^ hy1 ^ hz0) & TMASK;
        idx[7] = (ux1 ^ hy1 ^ hz1) & TMASK;

        const float wx0 = 1.0f - dx, wx1 = dx;
        const float wy0 = 1.0f - dy, wy1 = dy;
        const float wz0 = 1.0f - dz, wz1 = dz;

        float w[8];
        w[0] = wx0 * wy0 * wz0;
        w[1] = wx0 * wy0 * wz1;
        w[2] = wx0 * wy1 * wz0;
        w[3] = wx0 * wy1 * wz1;
        w[4] = wx1 * wy0 * wz0;
        w[5] = wx1 * wy0 * wz1;
        w[6] = wx1 * wy1 * wz0;
        w[7] = wx1 * wy1 * wz1;

        const float2* tab = reinterpret_cast<const float2*>(tables)
                            + ((size_t)i << TBITS);

        // issue all 8 gathers before consuming (MLP)
        float2 e0 = __ldg(tab + idx[0]);
        float2 e1 = __ldg(tab + idx[1]);
        float2 e2 = __ldg(tab + idx[2]);
        float2 e3 = __ldg(tab + idx[3]);
        float2 e4 = __ldg(tab + idx[4]);
        float2 e5 = __ldg(tab + idx[5]);
        float2 e6 = __ldg(tab + idx[6]);
        float2 e7 = __ldg(tab + idx[7]);

        float f0 = w[0] * e0.x; float f1 = w[0] * e0.y;
        f0 += w[1] * e1.x; f1 += w[1] * e1.y;
        f0 += w[2] * e2.x; f1 += w[2] * e2.y;
        f0 += w[3] * e3.x; f1 += w[3] * e3.y;
        f0 += w[4] * e4.x; f1 += w[4] * e4.y;
        f0 += w[5] * e5.x; f1 += w[5] * e5.y;
        f0 += w[6] * e6.x; f1 += w[6] * e6.y;
        f0 += w[7] * e7.x; f1 += w[7] * e7.y;

        feats[2 * i]     = f0;
        feats[2 * i + 1] = f1;
    }

    const size_t pt = (size_t)n * NS + s;

    // ---- enc_pts : [NRAYS, NS, 32] ----
    {
        float4* o4 = reinterpret_cast<float4*>(out) + pt * 8;
        #pragma unroll
        for (int j = 0; j < 8; ++j) {
            o4[j] = make_float4(feats[4 * j], feats[4 * j + 1],
                                feats[4 * j + 2], feats[4 * j + 3]);
        }
    }

    // ---- enc_dirs : [NRAYS, NS, 16] (same per ray) ----
    {
        const float x = dirx, y = diry, z = dirz;
        const float xx = x * x, yy = y * y, zz = z * z;
        const float xy = x * y, yz = y * z, xz = x * z;

        float sh[16];
        sh[0]  = 0.28209479177387814f;
        sh[1]  = -0.4886025119029199f * y;
        sh[2]  =  0.4886025119029199f * z;
        sh[3]  = -0.4886025119029199f * x;
        sh[4]  =  1.0925484305920792f * xy;
        sh[5]  = -1.0925484305920792f * yz;
        sh[6]  =  0.31539156525252005f * (2.0f * zz - xx - yy);
        sh[7]  = -1.0925484305920792f * xz;
        sh[8]  =  0.5462742152960396f * (xx - yy);
        sh[9]  = -0.5900435899266435f * y * (3.0f * xx - yy);
        sh[10] =  2.890611442640554f  * xy * z;
        sh[11] = -0.4570457994644658f * y * (4.0f * zz - xx - yy);
        sh[12] =  0.3731763325901154f * z * (2.0f * zz - 3.0f * xx - 3.0f * yy);
        sh[13] = -0.4570457994644658f * x * (4.0f * zz - xx - yy);
        sh[14] =  1.445305721320277f  * z * (xx - yy);
        sh[15] = -0.5900435899266435f * x * (xx - 3.0f * yy);

        float* outd = out + (size_t)NRAYS * NS * 32;
        float4* o4 = reinterpret_cast<float4*>(outd) + pt * 4;
        #pragma unroll
        for (int j = 0; j < 4; ++j) {
            o4[j] = make_float4(sh[4 * j], sh[4 * j + 1],
                                sh[4 * j + 2], sh[4 * j + 3]);
        }
    }

    // ---- dists : [NRAYS, NS] ----
    {
        float* outdist = out + (size_t)NRAYS * NS * (32 + 16);
        float dist;
        if (s == NS - 1) {
            dist = 1e10f;
        } else {
            const float tm1 = 2.0f + (s - 1) * step;
            const float tp1 = 2.0f + (s + 1) * step;
            const float tp2 = 2.0f + (s + 2) * step;

            const float r0 = t_rand[pt];
            const float r1 = t_rand[pt + 1];

            const float lower0 = (s == 0) ? t : 0.5f * (tm1 + t);
            const float upper0 = 0.5f * (t + tp1);           // s < 127 here
            const float tj0 = lower0 + (upper0 - lower0) * r0;

            const float lower1 = 0.5f * (t + tp1);
            const float upper1 = (s + 1 == NS - 1) ? tp1 : 0.5f * (tp1 + tp2);
            const float tj1 = lower1 + (upper1 - lower1) * r1;

            dist = tj1 - tj0;
        }
        outdist[pt] = dist;
    }
}

extern "C" void kernel_launch(void* const* d_in, const int* in_sizes, int n_in,
                              void* d_out, int out_size)
{
    (void)in_sizes; (void)n_in; (void)out_size;

    const float* rays   = (const float*)d_in[0];
    const float* t_rand = (const float*)d_in[1];
    const float* tables = (const float*)d_in[2];
    float* out = (float*)d_out;

    // Replicate reference resolution computation in double precision
    // (same libm on the same host as the reference run).
    Cells cells;
    const double bg = exp((log(2048.0) - log(16.0)) / 15.0);
    for (int i = 0; i < NLEV; ++i) {
        const double res = floor(16.0 * pow(bg, (double)i));
        cells.c[i] = (float)(16.0 / res);
    }

    ngp_kernel<<<NRAYS, NS>>>(rays, t_rand, tables, out, cells);
}

// round 2
// speedup vs baseline: 1.0786x; 1.0786x over previous
#include <cuda_runtime.h>
#include <math.h>
#include <stdint.h>

#define NLEV 16
#define TBITS 19
#define TMASK ((1u << TBITS) - 1u)
#define NS 128
#define NRAYS 4096

#define P1 2654435761u
#define P2 805459861u

struct Consts { float cell[NLEV]; float inv[NLEV]; };

__global__ __launch_bounds__(128)
void ngp_kernel(const float* __restrict__ rays,
                const float* __restrict__ t_rand,
                const float* __restrict__ tables,
                float* __restrict__ out,
                Consts cst)
{
    const int n = blockIdx.x;
    const int s = threadIdx.x;

    const float* ray = rays + n * 6;
    const float dirx = ray[0], diry = ray[1], dirz = ray[2];
    const float ox   = ray[3], oy   = ray[4], oz   = ray[5];

    const float step = 4.0f / 127.0f;   // (FAR-NEAR)/(NUM_SAMPLE-1)
    const float t    = 2.0f + s * step;

    const float px = ox + dirx * t;
    const float py = oy + diry * t;
    const float pz = oz + dirz * t;

    const size_t pt = (size_t)n * NS + s;
    float4* outp4 = reinterpret_cast<float4*>(out) + pt * 8;

    // ---- enc_pts : 16 levels, store one float4 per 2 levels ----
    #pragma unroll
    for (int ip = 0; ip < 8; ++ip) {
        float f[4];
        #pragma unroll
        for (int k = 0; k < 2; ++k) {
            const int i = ip * 2 + k;
            const float cell = cst.cell[i];
            const float inv  = cst.inv[i];

            const float fx = floorf((px + 8.0f) * inv);
            const float fy = floorf((py + 8.0f) * inv);
            const float fz = floorf((pz + 8.0f) * inv);

            // d = (p - (fx*cell + BB_MIN)) / cell
            const float dx = (px - (fx * cell - 8.0f)) * inv;
            const float dy = (py - (fy * cell - 8.0f)) * inv;
            const float dz = (pz - (fz * cell - 8.0f)) * inv;

            const unsigned ux0 = (unsigned)(int)fx;
            const unsigned ux1 = ux0 + 1u;
            const bool oddx = (ux0 & 1u) != 0u;
            const unsigned hy0 = (unsigned)(int)fy * P1;
            const unsigned hy1 = hy0 + P1;
            const unsigned hz0 = (unsigned)(int)fz * P2;
            const unsigned hz1 = hz0 + P2;

            const float wx0 = 1.0f - dx, wx1 = dx;
            const float wy0 = 1.0f - dy, wy1 = dy;
            const float wz0 = 1.0f - dz, wz1 = dz;

            const float2* tab  = reinterpret_cast<const float2*>(tables)
                                 + ((size_t)i << TBITS);
            const float4* tab4 = reinterpret_cast<const float4*>(tables)
                                 + ((size_t)i << (TBITS - 1));

            unsigned h[4];
            h[0] = hy0 ^ hz0; h[1] = hy0 ^ hz1;
            h[2] = hy1 ^ hz0; h[3] = hy1 ^ hz1;

            float wyz[4];
            wyz[0] = wy0 * wz0; wyz[1] = wy0 * wz1;
            wyz[2] = wy1 * wz0; wyz[3] = wy1 * wz1;

            // Issue all gathers up front.
            unsigned a[4];
            float4 q[4];
            #pragma unroll
            for (int c = 0; c < 4; ++c) {
                a[c] = (ux0 ^ h[c]) & TMASK;
                q[c] = __ldg(tab4 + (a[c] >> 1));
            }
            float2 ebo[4];
            if (oddx) {
                #pragma unroll
                for (int c = 0; c < 4; ++c) {
                    const unsigned b = (ux1 ^ h[c]) & TMASK;
                    ebo[c] = __ldg(tab + b);
                }
            }

            float f0 = 0.0f, f1 = 0.0f;
            #pragma unroll
            for (int c = 0; c < 4; ++c) {
                const bool ahigh = (a[c] & 1u) != 0u;
                const float eax = ahigh ? q[c].z : q[c].x;
                const float eay = ahigh ? q[c].w : q[c].y;
                float ebx, eby;
                if (oddx) {
                    ebx = ebo[c].x; eby = ebo[c].y;
                } else {
                    ebx = ahigh ? q[c].x : q[c].z;
                    eby = ahigh ? q[c].y : q[c].w;
                }
                f0 += wyz[c] * (wx0 * eax + wx1 * ebx);
                f1 += wyz[c] * (wx0 * eay + wx1 * eby);
            }
            f[2 * k]     = f0;
            f[2 * k + 1] = f1;
        }
        outp4[ip] = make_float4(f[0], f[1], f[2], f[3]);
    }

    // ---- enc_dirs : [NRAYS, NS, 16] (same per ray) ----
    {
        const float x = dirx, y = diry, z = dirz;
        const float xx = x * x, yy = y * y, zz = z * z;
        const float xy = x * y, yz = y * z, xz = x * z;

        float sh[16];
        sh[0]  = 0.28209479177387814f;
        sh[1]  = -0.4886025119029199f * y;
        sh[2]  =  0.4886025119029199f * z;
        sh[3]  = -0.4886025119029199f * x;
        sh[4]  =  1.0925484305920792f * xy;
        sh[5]  = -1.0925484305920792f * yz;
        sh[6]  =  0.31539156525252005f * (2.0f * zz - xx - yy);
        sh[7]  = -1.0925484305920792f * xz;
        sh[8]  =  0.5462742152960396f * (xx - yy);
        sh[9]  = -0.5900435899266435f * y * (3.0f * xx - yy);
        sh[10] =  2.890611442640554f  * xy * z;
        sh[11] = -0.4570457994644658f * y * (4.0f * zz - xx - yy);
        sh[12] =  0.3731763325901154f * z * (2.0f * zz - 3.0f * xx - 3.0f * yy);
        sh[13] = -0.4570457994644658f * x * (4.0f * zz - xx - yy);
        sh[14] =  1.445305721320277f  * z * (xx - yy);
        sh[15] = -0.5900435899266435f * x * (xx - 3.0f * yy);

        float* outd = out + (size_t)NRAYS * NS * 32;
        float4* o4 = reinterpret_cast<float4*>(outd) + pt * 4;
        #pragma unroll
        for (int j = 0; j < 4; ++j) {
            o4[j] = make_float4(sh[4 * j], sh[4 * j + 1],
                                sh[4 * j + 2], sh[4 * j + 3]);
        }
    }

    // ---- dists : [NRAYS, NS] ----
    {
        float* outdist = out + (size_t)NRAYS * NS * (32 + 16);
        float dist;
        if (s == NS - 1) {
            dist = 1e10f;
        } else {
            const float tm1 = 2.0f + (s - 1) * step;
            const float tp1 = 2.0f + (s + 1) * step;
            const float tp2 = 2.0f + (s + 2) * step;

            const float r0 = t_rand[pt];
            const float r1 = t_rand[pt + 1];

            const float lower0 = (s == 0) ? t : 0.5f * (tm1 + t);
            const float upper0 = 0.5f * (t + tp1);           // s < 127 here
            const float tj0 = lower0 + (upper0 - lower0) * r0;

            const float lower1 = 0.5f * (t + tp1);
            const float upper1 = (s + 1 == NS - 1) ? tp1 : 0.5f * (tp1 + tp2);
            const float tj1 = lower1 + (upper1 - lower1) * r1;

            dist = tj1 - tj0;
        }
        outdist[pt] = dist;
    }
}

extern "C" void kernel_launch(void* const* d_in, const int* in_sizes, int n_in,
                              void* d_out, int out_size)
{
    (void)in_sizes; (void)n_in; (void)out_size;

    const float* rays   = (const float*)d_in[0];
    const float* t_rand = (const float*)d_in[1];
    const float* tables = (const float*)d_in[2];
    float* out = (float*)d_out;

    // Replicate reference resolution computation in double precision
    // (same libm on the same host as the reference run).
    Consts cst;
    const double bg = exp((log(2048.0) - log(16.0)) / 15.0);
    for (int i = 0; i < NLEV; ++i) {
        const double res = floor(16.0 * pow(bg, (double)i));
        cst.cell[i] = (float)(16.0 / res);
        cst.inv[i]  = (float)(res / 16.0);
    }

    ngp_kernel<<<NRAYS, NS>>>(rays, t_rand, tables, out, cst);
}